// round 10
// baseline (speedup 1.0000x reference)
#include <cuda_runtime.h>
#include <cuda_bf16.h>
#include <cstdint>

#define BB 32
#define CC 16
#define NN 64
#define TL 4096
#define OO 16
#define TT 128   // t-tile per CTA

// B operand of every mma, precomputed in fragment-register layout:
// g_Bfrag[((o*8 + nt)*4 + ks)*32 + lane] = {hi_b0, hi_b1, lo_b0, lo_b1}
// (nt, ks) tile the 64x64 M_o into n-tiles of 8 (i) and k-steps of 16 (j);
// (b0, b1) follow the PTX m16n8k16 B-fragment mapping:
//   b0 holds k = ks*16 + tig*2 + {0,1}, b1 holds k = ks*16 + tig*2 + {8,9},
//   n = nt*8 + gid (gid = lane>>2, tig = lane&3), low 16 bits = lower k.
// 256 KB total, L2-resident, broadcast across all warps/CTAs.
__device__ __align__(16) uint4 g_Bfrag[OO * 8 * 4 * 32];

// ---------------------------------------------------------------------------
// Kernel 1: precompute M in bf16 hi/lo fragment layout (smem-staged U/theta).
// M[o][j][i] = sum_n U[i,n] * theta[n,o] * U[j,n]
// ---------------------------------------------------------------------------
__global__ void compute_B_kernel(const float* __restrict__ U,
                                 const float* __restrict__ theta) {
    __shared__ float sU[64 * 64];    // 16 KB
    __shared__ float sT[64 * 16];    // 4 KB
    int t = threadIdx.x;
    for (int i = t; i < 4096; i += 256) sU[i] = U[i];
    for (int i = t; i < 1024; i += 256) sT[i] = theta[i];
    __syncthreads();

    int idx  = blockIdx.x * 256 + t;            // 0..16383
    int lane = idx & 31;
    int ks   = (idx >> 5) & 3;
    int nt   = (idx >> 7) & 7;
    int o    = idx >> 10;
    int gid  = lane >> 2, tig = lane & 3;
    int n    = nt * 8 + gid;            // i
    int kb   = ks * 16 + tig * 2;       // base j

    int j0 = kb, j1 = kb + 1, j2 = kb + 8, j3 = kb + 9;
    float a0 = 0.f, a1 = 0.f, a2 = 0.f, a3 = 0.f;
#pragma unroll
    for (int q = 0; q < 64; ++q) {
        float un = sU[n * 64 + q] * sT[q * 16 + o];
        a0 += un * sU[j0 * 64 + q];
        a1 += un * sU[j1 * 64 + q];
        a2 += un * sU[j2 * 64 + q];
        a3 += un * sU[j3 * 64 + q];
    }
    __nv_bfloat162 h0 = __floats2bfloat162_rn(a0, a1);  // .x = low k
    __nv_bfloat162 h1 = __floats2bfloat162_rn(a2, a3);
    __nv_bfloat162 l0 = __floats2bfloat162_rn(a0 - __bfloat162float(h0.x),
                                              a1 - __bfloat162float(h0.y));
    __nv_bfloat162 l1 = __floats2bfloat162_rn(a2 - __bfloat162float(h1.x),
                                              a3 - __bfloat162float(h1.y));
    uint4 v;
    v.x = *(unsigned*)&h0;
    v.y = *(unsigned*)&h1;
    v.z = *(unsigned*)&l0;
    v.w = *(unsigned*)&l1;
    g_Bfrag[idx] = v;
}

// ---------------------------------------------------------------------------
// mma.sync m16n8k16 bf16 (baseline PTX, assembles under compute_103)
// ---------------------------------------------------------------------------
__device__ __forceinline__ void mma16816(float* c, const unsigned* a,
                                         unsigned b0, unsigned b1) {
    asm volatile(
        "mma.sync.aligned.m16n8k16.row.col.f32.bf16.bf16.f32 "
        "{%0,%1,%2,%3}, {%4,%5,%6,%7}, {%8,%9}, {%0,%1,%2,%3};"
        : "+f"(c[0]), "+f"(c[1]), "+f"(c[2]), "+f"(c[3])
        : "r"(a[0]), "r"(a[1]), "r"(a[2]), "r"(a[3]), "r"(b0), "r"(b1));
}

// ---------------------------------------------------------------------------
// Kernel 2: per CTA = (b, 128-t tile), 128 threads (4 warps), 4 CTAs/SM.
//  Phase 1: channel-sum x -> smem xs[j=64][t=128] f32 (pitch 132).
//  Phase 2: each warp loads A fragments for TWO 16-row m-tiles (32 t rows),
//           bf16 hi/lo split (64 regs), reused for all 16 o.
//  Phase 3: per o, stream nt=0..7; B frags via LDG.128 (L1-resident).
//           Accumulation split into hh / ml chains (4 independent RAW chains
//           per warp, max length 8) to keep the tensor pipe fed.
//           Zero LDS in the hot loop.
// ---------------------------------------------------------------------------
#define PITCH 132   // floats per xs row (128 + 4 pad): STS.128 fills and the
                    // A-gather LDS.32 both hit 32 distinct banks

__global__ void __launch_bounds__(128, 4)
spectral_hmma_kernel(const float* __restrict__ x, float* __restrict__ y) {
    __shared__ float xs[NN * PITCH];   // 33792 B

    const int tid  = threadIdx.x;
    const int wid  = tid >> 5;
    const int lane = tid & 31;
    const int gid  = lane >> 2;
    const int tig  = lane & 3;
    const int b    = blockIdx.y;
    const int t0   = blockIdx.x * TT;

    // ---- Phase 1: channel sum -> xs[j][t]
#pragma unroll
    for (int k = 0; k < 16; ++k) {
        int eid = tid + k * 128;            // 0..2047 float4 elements
        int j   = eid >> 5;
        int tc  = eid & 31;                 // float4 column 0..31
        const float4* px =
            (const float4*)(x + ((size_t)b * CC * NN + j) * TL + t0) + tc;
        float4 s = make_float4(0.f, 0.f, 0.f, 0.f);
#pragma unroll
        for (int c = 0; c < CC; ++c) {
            float4 v = __ldcs(px + (size_t)c * (NN * (TL / 4)));
            s.x += v.x; s.y += v.y; s.z += v.z; s.w += v.w;
        }
        *(float4*)&xs[j * PITCH + tc * 4] = s;
    }
    __syncthreads();

    // ---- Phase 2: A fragments, 2 m-tiles per warp (t rows wid*32 .. +31)
    unsigned Ahi[2][4][4], Alo[2][4][4];
    {
        const int tb = wid * 32;
#pragma unroll
        for (int mt = 0; mt < 2; ++mt) {
#pragma unroll
            for (int ks = 0; ks < 4; ++ks) {
                int j0 = ks * 16 + tig * 2;
                int r0 = tb + mt * 16 + gid;
#pragma unroll
                for (int p = 0; p < 4; ++p) {
                    // p: 0->(r0,j0) 1->(r0+8,j0) 2->(r0,j0+8) 3->(r0+8,j0+8)
                    int rr = r0 + (p & 1) * 8;
                    int jj = j0 + (p >> 1) * 8;
                    float f0 = xs[jj * PITCH + rr];
                    float f1 = xs[(jj + 1) * PITCH + rr];
                    __nv_bfloat162 h = __floats2bfloat162_rn(f0, f1);
                    float q0 = f0 - __bfloat162float(h.x);
                    float q1 = f1 - __bfloat162float(h.y);
                    __nv_bfloat162 l = __floats2bfloat162_rn(q0, q1);
                    Ahi[mt][ks][p] = *(unsigned*)&h;
                    Alo[mt][ks][p] = *(unsigned*)&l;
                }
            }
        }
    }

    // ---- Phase 3: per-o GEMM + streaming store
    for (int o = 0; o < OO; ++o) {
        const uint4* bp = g_Bfrag + (size_t)o * (8 * 4 * 32) + lane;
        float* const yo = y + ((size_t)b * OO + o) * NN * TL + t0;

#pragma unroll
        for (int nt = 0; nt < 8; ++nt) {
            uint4 cur[4];
#pragma unroll
            for (int ks = 0; ks < 4; ++ks) cur[ks] = bp[(nt * 4 + ks) * 32];

            // hh: pure hi*hi chains (length 4); ml: hi*lo + lo*hi chains
            // (length 8). 4 independent RAW chains per warp.
            float hh[2][4] = {{0.f, 0.f, 0.f, 0.f}, {0.f, 0.f, 0.f, 0.f}};
            float ml[2][4] = {{0.f, 0.f, 0.f, 0.f}, {0.f, 0.f, 0.f, 0.f}};
#pragma unroll
            for (int ks = 0; ks < 4; ++ks) {
#pragma unroll
                for (int mt = 0; mt < 2; ++mt) {
                    mma16816(hh[mt], Ahi[mt][ks], cur[ks].x, cur[ks].y); // hi*hi
                    mma16816(ml[mt], Ahi[mt][ks], cur[ks].z, cur[ks].w); // hi*lo
                    mma16816(ml[mt], Alo[mt][ks], cur[ks].x, cur[ks].y); // lo*hi
                }
            }

            // combine + store:
            // c0 -> (i0, t), c1 -> (i0+1, t), c2 -> (i0, t+8), c3 -> (i0+1, t+8)
            int i0 = nt * 8 + tig * 2;
#pragma unroll
            for (int mt = 0; mt < 2; ++mt) {
                int tr = wid * 32 + mt * 16 + gid;
                float* yb = yo + (size_t)i0 * TL + tr;
                __stcs(yb,          hh[mt][0] + ml[mt][0]);
                __stcs(yb + TL,     hh[mt][1] + ml[mt][1]);
                __stcs(yb + 8,      hh[mt][2] + ml[mt][2]);
                __stcs(yb + TL + 8, hh[mt][3] + ml[mt][3]);
            }
        }
    }
}

// ---------------------------------------------------------------------------
// kernel_launch: graph-capturable, allocation-free.
// Inputs: x (B,C,N,T) f32, U (N,N) f32, theta (N,OUT) f32. Output y (B,OUT,N,T) f32.
// ---------------------------------------------------------------------------
extern "C" void kernel_launch(void* const* d_in, const int* in_sizes, int n_in,
                              void* d_out, int out_size) {
    const float* x     = (const float*)d_in[0];
    const float* U     = (const float*)d_in[1];
    const float* theta = (const float*)d_in[2];
    float* y = (float*)d_out;

    compute_B_kernel<<<64, 256>>>(U, theta);
    spectral_hmma_kernel<<<dim3(TL / TT, BB), 128>>>(x, y);
}